// round 1
// baseline (speedup 1.0000x reference)
#include <cuda_runtime.h>

// Problem constants (fixed shapes from the dataset)
#define H        51
#define G        204          // 4*H gates
#define HP       52           // padded hidden (multiple of 4; stride 52 is LDS.128 conflict-free)
#define NJ       13           // HP/4 float4 chunks
#define BB       4            // batch rows per block
#define TSTEPS   512
#define BTOT     512
#define NTH      224          // 7 warps (204 gate threads + spare)
#define NBLK     (BTOT/BB)    // 128 blocks -> single wave on 148 SMs

#define SMEM_FLOATS (3*G*HP + 2*BB*HP + 2*G*BB + 3*G + HP + BB)
#define SMEM_BYTES  (SMEM_FLOATS * 4)

__device__ __forceinline__ float sigf(float x) {
    // 1/(1+e^-x); saturates cleanly at 0/1 for large |x|
    return 1.0f / (1.0f + __expf(-x));
}
__device__ __forceinline__ float tanhfast(float x) {
    // tanh(x) = 1 - 2/(e^{2x}+1); no inf/inf NaN at large |x|
    return 1.0f - 2.0f / (__expf(2.0f * x) + 1.0f);
}

extern __shared__ float smem[];

__global__ __launch_bounds__(NTH, 1)
void lstm2_kernel(const float* __restrict__ input,
                  const float* __restrict__ W_ih1,
                  const float* __restrict__ W_hh1,
                  const float* __restrict__ b_ih1,
                  const float* __restrict__ b_hh1,
                  const float* __restrict__ W_ih2,
                  const float* __restrict__ W_hh2,
                  const float* __restrict__ b_ih2,
                  const float* __restrict__ b_hh2,
                  const float* __restrict__ W_lin,
                  const float* __restrict__ b_lin,
                  float* __restrict__ out)
{
    float* ws1    = smem;                 // [G][HP]  W_hh1 padded
    float* ws2a   = ws1   + G*HP;         // [G][HP]  W_ih2 padded
    float* ws2b   = ws2a  + G*HP;         // [G][HP]  W_hh2 padded
    float* h1s    = ws2b  + G*HP;         // [BB][HP] (pad stays 0)
    float* h2s    = h1s   + BB*HP;        // [BB][HP]
    float* z1s    = h2s   + BB*HP;        // [G][BB]
    float* z2s    = z1s   + G*BB;         // [G][BB]
    float* wih1s  = z2s   + G*BB;         // [G]
    float* bias1s = wih1s + G;            // [G]
    float* bias2s = bias1s+ G;            // [G]
    float* wlins  = bias2s+ G;            // [HP] (pad 0)
    float* xs     = wlins + HP;           // [BB]

    const int tid = threadIdx.x;

    // ---- stage weights into smem (once; amortized over 512 steps) ----
    for (int idx = tid; idx < G*HP; idx += NTH) {
        const int g = idx / HP;
        const int k = idx - g*HP;
        float v1 = 0.f, v2 = 0.f, v3 = 0.f;
        if (k < H) {
            v1 = W_hh1[g*H + k];
            v2 = W_ih2[g*H + k];
            v3 = W_hh2[g*H + k];
        }
        ws1[idx] = v1; ws2a[idx] = v2; ws2b[idx] = v3;
    }
    for (int g = tid; g < G; g += NTH) {
        wih1s[g]  = W_ih1[g];
        bias1s[g] = b_ih1[g] + b_hh1[g];
        bias2s[g] = b_ih2[g] + b_hh2[g];
    }
    if (tid < HP) wlins[tid] = (tid < H) ? W_lin[tid] : 0.0f;
    for (int i = tid; i < BB*HP; i += NTH) { h1s[i] = 0.f; h2s[i] = 0.f; }

    // fixed thread -> (batch, hidden) map for the combine phases
    const int cb = (tid < G) ? (tid / H) : 0;
    const int ch = (tid < G) ? (tid - cb*H) : 0;
    float c1 = 0.f, c2 = 0.f;            // cell states live in registers

    const int   row0 = blockIdx.x * BB;
    const float blin = b_lin[0];

    __syncthreads();

    for (int t = 0; t < TSTEPS; ++t) {
        if (tid < BB) xs[tid] = input[(row0 + tid)*TSTEPS + t];
        __syncthreads();

        // ---- layer-1 gate pre-activations: z1[g][b] ----
        if (tid < G) {
            const float bz = bias1s[tid];
            const float wx = wih1s[tid];
            float a0 = fmaf(xs[0], wx, bz);
            float a1 = fmaf(xs[1], wx, bz);
            float a2 = fmaf(xs[2], wx, bz);
            float a3 = fmaf(xs[3], wx, bz);
            const float4* wr = reinterpret_cast<const float4*>(ws1 + tid*HP);
            const float4* p0 = reinterpret_cast<const float4*>(h1s);
            const float4* p1 = reinterpret_cast<const float4*>(h1s + HP);
            const float4* p2 = reinterpret_cast<const float4*>(h1s + 2*HP);
            const float4* p3 = reinterpret_cast<const float4*>(h1s + 3*HP);
            #pragma unroll
            for (int j = 0; j < NJ; ++j) {
                const float4 w  = wr[j];
                const float4 u0 = p0[j], u1 = p1[j], u2 = p2[j], u3 = p3[j];
                a0 = fmaf(w.x,u0.x,a0); a0 = fmaf(w.y,u0.y,a0); a0 = fmaf(w.z,u0.z,a0); a0 = fmaf(w.w,u0.w,a0);
                a1 = fmaf(w.x,u1.x,a1); a1 = fmaf(w.y,u1.y,a1); a1 = fmaf(w.z,u1.z,a1); a1 = fmaf(w.w,u1.w,a1);
                a2 = fmaf(w.x,u2.x,a2); a2 = fmaf(w.y,u2.y,a2); a2 = fmaf(w.z,u2.z,a2); a2 = fmaf(w.w,u2.w,a2);
                a3 = fmaf(w.x,u3.x,a3); a3 = fmaf(w.y,u3.y,a3); a3 = fmaf(w.z,u3.z,a3); a3 = fmaf(w.w,u3.w,a3);
            }
            reinterpret_cast<float4*>(z1s)[tid] = make_float4(a0,a1,a2,a3);
        }
        __syncthreads();

        // ---- layer-1 combine: c1, h1 ----
        if (tid < G) {
            const float zi = z1s[ ch         *BB + cb];
            const float zf = z1s[(ch +   H ) *BB + cb];
            const float zg = z1s[(ch + 2*H ) *BB + cb];
            const float zo = z1s[(ch + 3*H ) *BB + cb];
            const float ig = sigf(zi);
            const float fg = sigf(zf);
            const float gg = tanhfast(zg);
            const float og = sigf(zo);
            c1 = fmaf(fg, c1, ig*gg);
            h1s[cb*HP + ch] = og * tanhfast(c1);
        }
        __syncthreads();

        // ---- layer-2 gate pre-activations: z2[g][b] ----
        if (tid < G) {
            float a0 = bias2s[tid];
            float a1 = a0, a2 = a0, a3 = a0;
            const float4* wa = reinterpret_cast<const float4*>(ws2a + tid*HP);
            const float4* wb = reinterpret_cast<const float4*>(ws2b + tid*HP);
            const float4* p0 = reinterpret_cast<const float4*>(h1s);
            const float4* p1 = reinterpret_cast<const float4*>(h1s + HP);
            const float4* p2 = reinterpret_cast<const float4*>(h1s + 2*HP);
            const float4* p3 = reinterpret_cast<const float4*>(h1s + 3*HP);
            const float4* q0 = reinterpret_cast<const float4*>(h2s);
            const float4* q1 = reinterpret_cast<const float4*>(h2s + HP);
            const float4* q2 = reinterpret_cast<const float4*>(h2s + 2*HP);
            const float4* q3 = reinterpret_cast<const float4*>(h2s + 3*HP);
            #pragma unroll
            for (int j = 0; j < NJ; ++j) {
                {
                    const float4 w  = wa[j];
                    const float4 u0 = p0[j], u1 = p1[j], u2 = p2[j], u3 = p3[j];
                    a0 = fmaf(w.x,u0.x,a0); a0 = fmaf(w.y,u0.y,a0); a0 = fmaf(w.z,u0.z,a0); a0 = fmaf(w.w,u0.w,a0);
                    a1 = fmaf(w.x,u1.x,a1); a1 = fmaf(w.y,u1.y,a1); a1 = fmaf(w.z,u1.z,a1); a1 = fmaf(w.w,u1.w,a1);
                    a2 = fmaf(w.x,u2.x,a2); a2 = fmaf(w.y,u2.y,a2); a2 = fmaf(w.z,u2.z,a2); a2 = fmaf(w.w,u2.w,a2);
                    a3 = fmaf(w.x,u3.x,a3); a3 = fmaf(w.y,u3.y,a3); a3 = fmaf(w.z,u3.z,a3); a3 = fmaf(w.w,u3.w,a3);
                }
                {
                    const float4 w  = wb[j];
                    const float4 u0 = q0[j], u1 = q1[j], u2 = q2[j], u3 = q3[j];
                    a0 = fmaf(w.x,u0.x,a0); a0 = fmaf(w.y,u0.y,a0); a0 = fmaf(w.z,u0.z,a0); a0 = fmaf(w.w,u0.w,a0);
                    a1 = fmaf(w.x,u1.x,a1); a1 = fmaf(w.y,u1.y,a1); a1 = fmaf(w.z,u1.z,a1); a1 = fmaf(w.w,u1.w,a1);
                    a2 = fmaf(w.x,u2.x,a2); a2 = fmaf(w.y,u2.y,a2); a2 = fmaf(w.z,u2.z,a2); a2 = fmaf(w.w,u2.w,a2);
                    a3 = fmaf(w.x,u3.x,a3); a3 = fmaf(w.y,u3.y,a3); a3 = fmaf(w.z,u3.z,a3); a3 = fmaf(w.w,u3.w,a3);
                }
            }
            reinterpret_cast<float4*>(z2s)[tid] = make_float4(a0,a1,a2,a3);
        }
        __syncthreads();

        // ---- layer-2 combine: c2, h2 ----
        if (tid < G) {
            const float zi = z2s[ ch         *BB + cb];
            const float zf = z2s[(ch +   H ) *BB + cb];
            const float zg = z2s[(ch + 2*H ) *BB + cb];
            const float zo = z2s[(ch + 3*H ) *BB + cb];
            const float ig = sigf(zi);
            const float fg = sigf(zf);
            const float gg = tanhfast(zg);
            const float og = sigf(zo);
            c2 = fmaf(fg, c2, ig*gg);
            h2s[cb*HP + ch] = og * tanhfast(c2);
        }
        __syncthreads();

        // ---- output head: out[b][t] = h2 . W_lin + b_lin (warps 0-3, one per batch row) ----
        if (tid < 128) {
            const int b = tid >> 5;
            const int l = tid & 31;
            float v = h2s[b*HP + l] * wlins[l];
            if (l + 32 < H) v = fmaf(h2s[b*HP + l + 32], wlins[l + 32], v);
            #pragma unroll
            for (int off = 16; off; off >>= 1)
                v += __shfl_down_sync(0xffffffffu, v, off);
            if (l == 0) out[(row0 + b)*TSTEPS + t] = v + blin;
        }
        // next-iter xs store + top sync provide the needed ordering
    }
}

extern "C" void kernel_launch(void* const* d_in, const int* in_sizes, int n_in,
                              void* d_out, int out_size)
{
    const float* input = (const float*)d_in[0];
    const float* W_ih1 = (const float*)d_in[1];
    const float* W_hh1 = (const float*)d_in[2];
    const float* b_ih1 = (const float*)d_in[3];
    const float* b_hh1 = (const float*)d_in[4];
    const float* W_ih2 = (const float*)d_in[5];
    const float* W_hh2 = (const float*)d_in[6];
    const float* b_ih2 = (const float*)d_in[7];
    const float* b_hh2 = (const float*)d_in[8];
    const float* W_lin = (const float*)d_in[9];
    const float* b_lin = (const float*)d_in[10];
    float* out = (float*)d_out;

    cudaFuncSetAttribute(lstm2_kernel,
                         cudaFuncAttributeMaxDynamicSharedMemorySize, SMEM_BYTES);
    lstm2_kernel<<<NBLK, NTH, SMEM_BYTES>>>(input, W_ih1, W_hh1, b_ih1, b_hh1,
                                            W_ih2, W_hh2, b_ih2, b_hh2,
                                            W_lin, b_lin, out);
}

// round 2
// speedup vs baseline: 1.0369x; 1.0369x over previous
#include <cuda_runtime.h>

// 2-layer LSTM, H=51, B=512, T=512, scalar input, linear head. future=0.
// 128 persistent blocks (BB=4 batch rows each), 448 threads = 2 K-split groups.
// f32x2 packed FMAs; layer-2 weights in registers; x preloaded; 4 barriers/step.

#define H     51
#define G     204            // 4*H
#define HP    52             // padded row (13 float4 chunks; stride 52 is LDS.128 conflict-free)
#define BB    4
#define TSTEPS 512
#define NTH   448            // 14 warps: group A = tid<224, group B = tid>=224
#define NBLK  128

// smem layout (floats)
#define OFF_WS1   0
#define OFF_H1    (G*HP)                 // BB*HP + 4 pad
#define OFF_H2    (OFF_H1 + BB*HP + 4)
#define OFF_ZPS   (OFF_H2 + BB*HP + 4)   // [2][G][BB]
#define OFF_XALL  (OFF_ZPS + 2*G*BB)     // [BB][TSTEPS]
#define SMEM_FLOATS (OFF_XALL + BB*TSTEPS)
#define SMEM_BYTES  (SMEM_FLOATS*4)

typedef unsigned long long ull;

__device__ __forceinline__ ull fma2(ull a, ull b, ull c) {
    ull d; asm("fma.rn.f32x2 %0, %1, %2, %3;" : "=l"(d) : "l"(a), "l"(b), "l"(c)); return d;
}
__device__ __forceinline__ ull add2(ull a, ull b) {
    ull d; asm("add.rn.f32x2 %0, %1, %2;" : "=l"(d) : "l"(a), "l"(b)); return d;
}
__device__ __forceinline__ ull pack2(float lo, float hi) {
    ull d; asm("mov.b64 %0, {%1, %2};" : "=l"(d) : "f"(lo), "f"(hi)); return d;
}
__device__ __forceinline__ float sum2(ull a) {
    float x, y; asm("mov.b64 {%0, %1}, %2;" : "=f"(x), "=f"(y) : "l"(a)); return x + y;
}
__device__ __forceinline__ float sigf(float x) {
    return 1.0f / (1.0f + __expf(-x));
}
__device__ __forceinline__ float tanhfast(float x) {
    return 1.0f - 2.0f / (__expf(2.0f * x) + 1.0f);
}

extern __shared__ float smem[];

__global__ __launch_bounds__(NTH, 1)
void lstm2_kernel(const float* __restrict__ input,
                  const float* __restrict__ W_ih1,
                  const float* __restrict__ W_hh1,
                  const float* __restrict__ b_ih1,
                  const float* __restrict__ b_hh1,
                  const float* __restrict__ W_ih2,
                  const float* __restrict__ W_hh2,
                  const float* __restrict__ b_ih2,
                  const float* __restrict__ b_hh2,
                  const float* __restrict__ W_lin,
                  const float* __restrict__ b_lin,
                  float* __restrict__ out)
{
    float* ws1  = smem + OFF_WS1;
    float* h1s  = smem + OFF_H1;
    float* h2s  = smem + OFF_H2;
    float* zps  = smem + OFF_ZPS;
    float* xall = smem + OFF_XALL;

    const int tid  = threadIdx.x;
    const int grp  = (tid >= 224);
    const int lt   = grp ? tid - 224 : tid;
    const bool act = (lt < G);
    const int g    = lt;
    const int row0 = blockIdx.x * BB;

    // ---- stage W_hh1 (padded rows) ----
    for (int idx = tid; idx < G*HP; idx += NTH) {
        const int gg = idx / HP;
        const int k  = idx - gg*HP;
        ws1[idx] = (k < H) ? W_hh1[gg*H + k] : 0.0f;
    }
    // zero h buffers + pads
    for (int i = tid; i < BB*HP + 4; i += NTH) { h1s[i] = 0.0f; h2s[i] = 0.0f; }
    // preload all x (coalesced)
    for (int i = tid; i < BB*TSTEPS; i += NTH) {
        const int b = i >> 9;            // TSTEPS = 512
        const int t = i & (TSTEPS - 1);
        xall[i] = input[(row0 + b)*TSTEPS + t];
    }

    // ---- per-thread invariants ----
    float wx = 0.f, bz1 = 0.f, bz2 = 0.f;
    if (act) {
        wx  = W_ih1[g];
        bz1 = b_ih1[g] + b_hh1[g];
        bz2 = b_ih2[g] + b_hh2[g];
    }

    // layer-2 weights -> registers as f32x2 pairs. Group A: j=0..6, group B: j=7..12 (+1 zero slot)
    ull wax[7], way[7], wbx[7], wby[7];
    #pragma unroll
    for (int jj = 0; jj < 7; ++jj) {
        float a0=0.f,a1=0.f,a2=0.f,a3=0.f, c0=0.f,c1_=0.f,c2_=0.f,c3=0.f;
        const int j = grp ? (7 + jj) : jj;
        if (act && j < 13) {
            const int k = 4*j;
            a0 = W_ih2[g*H + k];
            if (k+1 < H) a1 = W_ih2[g*H + k+1];
            if (k+2 < H) a2 = W_ih2[g*H + k+2];
            if (k+3 < H) a3 = W_ih2[g*H + k+3];
            c0 = W_hh2[g*H + k];
            if (k+1 < H) c1_ = W_hh2[g*H + k+1];
            if (k+2 < H) c2_ = W_hh2[g*H + k+2];
            if (k+3 < H) c3 = W_hh2[g*H + k+3];
        }
        wax[jj] = pack2(a0, a1); way[jj] = pack2(a2, a3);
        wbx[jj] = pack2(c0, c1_); wby[jj] = pack2(c2_, c3);
    }

    // combine mapping: 204 (b,h) items split: A handles 0..101 (b=0,1), B handles 102..203 (b=2,3)
    const int citem = grp ? (102 + lt) : lt;
    const bool cact = (lt < 102);
    const int cb  = citem / H;
    const int chh = citem - cb*H;
    float c1 = 0.f, c2 = 0.f;

    // out-head: warps 0-3 of group A; lane l covers h = l and l+32
    float wlo = 0.f, whi = 0.f, blinr = 0.f;
    const int ob = tid >> 5, ol = tid & 31;
    if (tid < 128) {
        wlo = W_lin[ol];
        if (ol + 32 < H) whi = W_lin[ol + 32];
        blinr = b_lin[0];
    }

    __syncthreads();

    for (int t = 0; t < TSTEPS; ++t) {
        // ======== layer-1 gate partials ========
        if (act) {
            ull aA[4], aB[4];
            const float* wr = ws1 + g*HP;
            if (!grp) {
                #pragma unroll
                for (int b = 0; b < 4; ++b) {
                    aA[b] = pack2(fmaf(xall[b*TSTEPS + t], wx, bz1), 0.0f);
                    aB[b] = 0ull;
                }
                #pragma unroll
                for (int j = 0; j < 6; ++j) {
                    const ulonglong2 w = *reinterpret_cast<const ulonglong2*>(wr + 4*j);
                    #pragma unroll
                    for (int b = 0; b < 4; ++b) {
                        const ulonglong2 u = *reinterpret_cast<const ulonglong2*>(h1s + b*HP + 4*j);
                        aA[b] = fma2(w.x, u.x, aA[b]);
                        aB[b] = fma2(w.y, u.y, aB[b]);
                    }
                }
            } else {
                #pragma unroll
                for (int b = 0; b < 4; ++b) { aA[b] = 0ull; aB[b] = 0ull; }
                #pragma unroll
                for (int j = 6; j < 13; ++j) {
                    const ulonglong2 w = *reinterpret_cast<const ulonglong2*>(wr + 4*j);
                    #pragma unroll
                    for (int b = 0; b < 4; ++b) {
                        const ulonglong2 u = *reinterpret_cast<const ulonglong2*>(h1s + b*HP + 4*j);
                        aA[b] = fma2(w.x, u.x, aA[b]);
                        aB[b] = fma2(w.y, u.y, aB[b]);
                    }
                }
            }
            float4 z4;
            z4.x = sum2(add2(aA[0], aB[0]));
            z4.y = sum2(add2(aA[1], aB[1]));
            z4.z = sum2(add2(aA[2], aB[2]));
            z4.w = sum2(add2(aA[3], aB[3]));
            reinterpret_cast<float4*>(zps)[grp*G + g] = z4;
        }
        __syncthreads();

        // ======== layer-1 combine ========
        if (cact) {
            const float zi = zps[(chh      )*4 + cb] + zps[(G + chh      )*4 + cb];
            const float zf = zps[(chh +   H)*4 + cb] + zps[(G + chh +   H)*4 + cb];
            const float zg = zps[(chh + 2*H)*4 + cb] + zps[(G + chh + 2*H)*4 + cb];
            const float zo = zps[(chh + 3*H)*4 + cb] + zps[(G + chh + 3*H)*4 + cb];
            const float ig = sigf(zi), fg = sigf(zf);
            const float gg = tanhfast(zg), og = sigf(zo);
            c1 = fmaf(fg, c1, ig*gg);
            h1s[cb*HP + chh] = og * tanhfast(c1);
        }
        __syncthreads();

        // ======== layer-2 gate partials (weights in regs) ========
        if (act) {
            ull aA[4], aB[4];
            #pragma unroll
            for (int b = 0; b < 4; ++b) {
                aA[b] = grp ? 0ull : pack2(bz2, 0.0f);
                aB[b] = 0ull;
            }
            const int jb = grp ? 28 : 0;   // float offset base = 4*j0
            #pragma unroll
            for (int jj = 0; jj < 7; ++jj) {
                const int j4 = jb + 4*jj;
                #pragma unroll
                for (int b = 0; b < 4; ++b) {
                    const ulonglong2 u = *reinterpret_cast<const ulonglong2*>(h1s + b*HP + j4);
                    aA[b] = fma2(wax[jj], u.x, aA[b]);
                    aB[b] = fma2(way[jj], u.y, aB[b]);
                }
                #pragma unroll
                for (int b = 0; b < 4; ++b) {
                    const ulonglong2 v = *reinterpret_cast<const ulonglong2*>(h2s + b*HP + j4);
                    aA[b] = fma2(wbx[jj], v.x, aA[b]);
                    aB[b] = fma2(wby[jj], v.y, aB[b]);
                }
            }
            float4 z4;
            z4.x = sum2(add2(aA[0], aB[0]));
            z4.y = sum2(add2(aA[1], aB[1]));
            z4.z = sum2(add2(aA[2], aB[2]));
            z4.w = sum2(add2(aA[3], aB[3]));
            reinterpret_cast<float4*>(zps)[grp*G + g] = z4;
        }
        __syncthreads();

        // ======== layer-2 combine ========
        if (cact) {
            const float zi = zps[(chh      )*4 + cb] + zps[(G + chh      )*4 + cb];
            const float zf = zps[(chh +   H)*4 + cb] + zps[(G + chh +   H)*4 + cb];
            const float zg = zps[(chh + 2*H)*4 + cb] + zps[(G + chh + 2*H)*4 + cb];
            const float zo = zps[(chh + 3*H)*4 + cb] + zps[(G + chh + 3*H)*4 + cb];
            const float ig = sigf(zi), fg = sigf(zf);
            const float gg = tanhfast(zg), og = sigf(zo);
            c2 = fmaf(fg, c2, ig*gg);
            h2s[cb*HP + chh] = og * tanhfast(c2);
        }
        __syncthreads();

        // ======== output head (no extra barrier: protected by B1..B3 of next iter) ========
        if (tid < 128) {
            float v = h2s[ob*HP + ol] * wlo;
            if (ol + 32 < H) v = fmaf(h2s[ob*HP + ol + 32], whi, v);
            #pragma unroll
            for (int off = 16; off; off >>= 1)
                v += __shfl_down_sync(0xffffffffu, v, off);
            if (ol == 0) out[(row0 + ob)*TSTEPS + t] = v + blinr;
        }
    }
}

extern "C" void kernel_launch(void* const* d_in, const int* in_sizes, int n_in,
                              void* d_out, int out_size)
{
    const float* input = (const float*)d_in[0];
    const float* W_ih1 = (const float*)d_in[1];
    const float* W_hh1 = (const float*)d_in[2];
    const float* b_ih1 = (const float*)d_in[3];
    const float* b_hh1 = (const float*)d_in[4];
    const float* W_ih2 = (const float*)d_in[5];
    const float* W_hh2 = (const float*)d_in[6];
    const float* b_ih2 = (const float*)d_in[7];
    const float* b_hh2 = (const float*)d_in[8];
    const float* W_lin = (const float*)d_in[9];
    const float* b_lin = (const float*)d_in[10];
    float* out = (float*)d_out;

    cudaFuncSetAttribute(lstm2_kernel,
                         cudaFuncAttributeMaxDynamicSharedMemorySize, SMEM_BYTES);
    lstm2_kernel<<<NBLK, NTH, SMEM_BYTES>>>(input, W_ih1, W_hh1, b_ih1, b_hh1,
                                            W_ih2, W_hh2, b_ih2, b_hh2,
                                            W_lin, b_lin, out);
}

// round 3
// speedup vs baseline: 1.2831x; 1.2375x over previous
#include <cuda_runtime.h>

// 2-layer LSTM (H=51), B=512, T=512, scalar input, linear head, future=0.
// 128 persistent blocks, BB=4 rows each, 672 threads.
// Software pipeline: layer-2 lags layer-1 by one step so all three matmuls
// (Whh1*h1, Wih2*h1, Whh2*h2) run concurrently in one phase. 2 barriers/step.
// Every matmul thread owns one full weight row in registers (26 f32x2 regs).

#define H      51
#define G      204
#define HP     52
#define BB     4
#define TT     512
#define NTH    672
#define NBLK   128
#define NITER  514

typedef unsigned long long ull;

__device__ __forceinline__ ull fma2(ull a, ull b, ull c) {
    ull d; asm("fma.rn.f32x2 %0, %1, %2, %3;" : "=l"(d) : "l"(a), "l"(b), "l"(c)); return d;
}
__device__ __forceinline__ ull add2(ull a, ull b) {
    ull d; asm("add.rn.f32x2 %0, %1, %2;" : "=l"(d) : "l"(a), "l"(b)); return d;
}
__device__ __forceinline__ ull pack2(float lo, float hi) {
    ull d; asm("mov.b64 %0, {%1, %2};" : "=l"(d) : "f"(lo), "f"(hi)); return d;
}
__device__ __forceinline__ float sum2(ull a) {
    float x, y; asm("mov.b64 {%0, %1}, %2;" : "=f"(x), "=f"(y) : "l"(a)); return x + y;
}
__device__ __forceinline__ float sigf(float x)     { return 1.0f / (1.0f + __expf(-x)); }
__device__ __forceinline__ float tanhfast(float x) { return 1.0f - 2.0f / (__expf(2.0f * x) + 1.0f); }

__global__ __launch_bounds__(NTH, 1)
void lstm2_kernel(const float* __restrict__ input,
                  const float* __restrict__ W_ih1,
                  const float* __restrict__ W_hh1,
                  const float* __restrict__ b_ih1,
                  const float* __restrict__ b_hh1,
                  const float* __restrict__ W_ih2,
                  const float* __restrict__ W_hh2,
                  const float* __restrict__ b_ih2,
                  const float* __restrict__ b_hh2,
                  const float* __restrict__ W_lin,
                  const float* __restrict__ b_lin,
                  float* __restrict__ out)
{
    __shared__ float h1s[BB*HP + 4];     // h1(t') rows of HP (pad elem 51 = 0)
    __shared__ float h2s[BB*HP + 4];     // h2(t')
    __shared__ float z1s[G*4];           // layer-1 gate preacts, float4 per gate
    __shared__ float zis[G*4];           // Wih2*h1 partial (+bias2)
    __shared__ float zhs[G*4];           // Whh2*h2 partial
    __shared__ float xall[BB*TT];        // preloaded inputs

    const int tid  = threadIdx.x;
    const int row0 = blockIdx.x * BB;

    const bool isL1  = (tid < 204);
    const bool isL2i = (tid >= 204 && tid < 408);
    const bool isL2h = (tid >= 408 && tid < 612);
    const bool isMM  = (tid < 612);
    const bool isOut = (tid >= 640);

    const int g = isL1 ? tid : (isL2i ? tid - 204 : (isL2h ? tid - 408 : 0));

    // ---- init smem ----
    for (int i = tid; i < BB*HP + 4; i += NTH) { h1s[i] = 0.0f; h2s[i] = 0.0f; }
    for (int i = tid; i < BB*TT; i += NTH) {
        const int b = i >> 9;              // TT = 512
        const int t = i & (TT - 1);
        xall[i] = input[(row0 + b)*TT + t];
    }

    // ---- weight row -> registers (26 f32x2) ----
    const float* wsrc = isL2i ? (W_ih2 + g*H) : (isL2h ? (W_hh2 + g*H) : (W_hh1 + g*H));
    ull w2[26];
    #pragma unroll
    for (int i = 0; i < 25; ++i) w2[i] = pack2(wsrc[2*i], wsrc[2*i + 1]);
    w2[25] = pack2(wsrc[50], 0.0f);

    float wx = 0.f, bz = 0.f;
    if (isL1)  { wx = W_ih1[g]; bz = b_ih1[g] + b_hh1[g]; }
    if (isL2i) { bz = b_ih2[g] + b_hh2[g]; }

    const float* hbase = isL2h ? h2s : h1s;
    float* zout = isL1 ? z1s : (isL2i ? zis : zhs);

    // combine mapping
    const int cit = isL1 ? tid : (tid - 204);       // 0..203
    const int cbb = cit / H;
    const int chh = cit - cbb*H;
    float c1 = 0.f, c2 = 0.f;

    // out head (warp 20): lane -> (batch = l>>3, slot = l&7), 7 weights each
    float wo[7]; float blin = 0.f;
    int ob = 0, oi = 0;
    if (isOut) {
        const int l = tid - 640;
        ob = l >> 3; oi = l & 7;
        #pragma unroll
        for (int m = 0; m < 7; ++m) {
            const int j = oi + 8*m;
            wo[m] = (j < H) ? W_lin[j] : 0.0f;
        }
        blin = b_lin[0];
    }

    __syncthreads();

    for (int t = 0; t < NITER; ++t) {
        // ================= Stage A: all three matmuls + out head =================
        const bool mmAct = isMM && (isL1 ? (t < 512) : (t >= 1 && t <= 512));
        if (mmAct) {
            float ini = bz;
            ull a0a, a1a, a2a, a3a, a0b, a1b, a2b, a3b;
            if (isL1) {
                a0a = pack2(fmaf(xall[0*TT + t], wx, ini), 0.f);
                a1a = pack2(fmaf(xall[1*TT + t], wx, ini), 0.f);
                a2a = pack2(fmaf(xall[2*TT + t], wx, ini), 0.f);
                a3a = pack2(fmaf(xall[3*TT + t], wx, ini), 0.f);
            } else {
                a0a = pack2(ini, 0.f); a1a = a0a; a2a = a0a; a3a = a0a;
            }
            a0b = 0ull; a1b = 0ull; a2b = 0ull; a3b = 0ull;

            #pragma unroll
            for (int j = 0; j < 13; ++j) {
                const ulonglong2 u0 = *reinterpret_cast<const ulonglong2*>(hbase + 0*HP + 4*j);
                const ulonglong2 u1 = *reinterpret_cast<const ulonglong2*>(hbase + 1*HP + 4*j);
                const ulonglong2 u2 = *reinterpret_cast<const ulonglong2*>(hbase + 2*HP + 4*j);
                const ulonglong2 u3 = *reinterpret_cast<const ulonglong2*>(hbase + 3*HP + 4*j);
                a0a = fma2(w2[2*j],   u0.x, a0a);  a0b = fma2(w2[2*j+1], u0.y, a0b);
                a1a = fma2(w2[2*j],   u1.x, a1a);  a1b = fma2(w2[2*j+1], u1.y, a1b);
                a2a = fma2(w2[2*j],   u2.x, a2a);  a2b = fma2(w2[2*j+1], u2.y, a2b);
                a3a = fma2(w2[2*j],   u3.x, a3a);  a3b = fma2(w2[2*j+1], u3.y, a3b);
            }
            float4 z4;
            z4.x = sum2(add2(a0a, a0b));
            z4.y = sum2(add2(a1a, a1b));
            z4.z = sum2(add2(a2a, a2b));
            z4.w = sum2(add2(a3a, a3b));
            reinterpret_cast<float4*>(zout)[g] = z4;
        }
        if (isOut && t >= 2) {
            // out(t-2) from h2s = h2(t-2)
            float v = 0.f;
            #pragma unroll
            for (int m = 0; m < 7; ++m) {
                const int j = oi + 8*m;
                if (j < H) v = fmaf(h2s[ob*HP + j], wo[m], v);
            }
            v += __shfl_xor_sync(0xffffffffu, v, 1);
            v += __shfl_xor_sync(0xffffffffu, v, 2);
            v += __shfl_xor_sync(0xffffffffu, v, 4);
            if (oi == 0) out[(row0 + ob)*TT + (t - 2)] = v + blin;
        }
        __syncthreads();

        // ================= Stage B: combines =================
        if (isL1 && t < 512) {
            const float zi = z1s[4*(chh        ) + cbb];
            const float zf = z1s[4*(chh +   H  ) + cbb];
            const float zg = z1s[4*(chh + 2*H  ) + cbb];
            const float zo = z1s[4*(chh + 3*H  ) + cbb];
            const float ig = sigf(zi), fg = sigf(zf);
            const float gg = tanhfast(zg), og = sigf(zo);
            c1 = fmaf(fg, c1, ig*gg);
            h1s[cbb*HP + chh] = og * tanhfast(c1);
        } else if (isL2i && t >= 1 && t <= 512) {
            const float zi = zis[4*(chh        ) + cbb] + zhs[4*(chh        ) + cbb];
            const float zf = zis[4*(chh +   H  ) + cbb] + zhs[4*(chh +   H  ) + cbb];
            const float zg = zis[4*(chh + 2*H  ) + cbb] + zhs[4*(chh + 2*H  ) + cbb];
            const float zo = zis[4*(chh + 3*H  ) + cbb] + zhs[4*(chh + 3*H  ) + cbb];
            const float ig = sigf(zi), fg = sigf(zf);
            const float gg = tanhfast(zg), og = sigf(zo);
            c2 = fmaf(fg, c2, ig*gg);
            h2s[cbb*HP + chh] = og * tanhfast(c2);
        }
        __syncthreads();
    }
}

extern "C" void kernel_launch(void* const* d_in, const int* in_sizes, int n_in,
                              void* d_out, int out_size)
{
    const float* input = (const float*)d_in[0];
    const float* W_ih1 = (const float*)d_in[1];
    const float* W_hh1 = (const float*)d_in[2];
    const float* b_ih1 = (const float*)d_in[3];
    const float* b_hh1 = (const float*)d_in[4];
    const float* W_ih2 = (const float*)d_in[5];
    const float* W_hh2 = (const float*)d_in[6];
    const float* b_ih2 = (const float*)d_in[7];
    const float* b_hh2 = (const float*)d_in[8];
    const float* W_lin = (const float*)d_in[9];
    const float* b_lin = (const float*)d_in[10];
    float* out = (float*)d_out;

    lstm2_kernel<<<NBLK, NTH>>>(input, W_ih1, W_hh1, b_ih1, b_hh1,
                                W_ih2, W_hh2, b_ih2, b_hh2,
                                W_lin, b_lin, out);
}